// round 13
// baseline (speedup 1.0000x reference)
#include <cuda_runtime.h>
#include <cuda_fp16.h>
#include <cstdint>
#include <cstddef>

#define NN 50000
#define NE 800000
#define CONV_BLKS ((NN * 32 + 255) / 256)
#define NB 148
#define CSR_T 256
#define CHUNK 338   // 148*338 = 50024 >= 50000

// ---------------- scratch (static device globals) ----------------
__device__ int   g_cnt[NN];
__device__ int   g_rowptr[NN + 1];
__device__ int   g_wr[NN];
__device__ int   g_csr[NE];
__device__ float g_dinv[NN];
__device__ __half g_xh[(size_t)NN * 128];
__device__ __half g_ylh[(size_t)NN * 128];
__device__ float  g_yrf[(size_t)NN * 128];
__device__ __half g_wt[2 * 256 * 128 + 128 * 128];   // L0,L1: 256x128 ; L2: 128x128
__device__ unsigned g_bgen = 0;
__device__ unsigned g_bcnt = 0;
__device__ int g_bsum[NB];
__device__ int g_boff[NB];

// ---------------- PTX helpers (base ISA only) ----------------
__device__ __forceinline__ uint32_t su32(const void* p) {
    uint32_t a;
    asm("{ .reg .u64 t; cvta.to.shared.u64 t, %1; cvt.u32.u64 %0, t; }" : "=r"(a) : "l"(p));
    return a;
}
__device__ __forceinline__ void ldsm4(uint32_t* r, uint32_t addr) {
    asm volatile("ldmatrix.sync.aligned.m8n8.x4.shared.b16 {%0,%1,%2,%3}, [%4];"
                 : "=r"(r[0]), "=r"(r[1]), "=r"(r[2]), "=r"(r[3]) : "r"(addr));
}
__device__ __forceinline__ void mma16816h(float* d, const uint32_t* a, const uint32_t* b) {
    asm volatile(
        "mma.sync.aligned.m16n8k16.row.col.f32.f16.f16.f32 "
        "{%0,%1,%2,%3}, {%4,%5,%6,%7}, {%8,%9}, {%0,%1,%2,%3};"
        : "+f"(d[0]), "+f"(d[1]), "+f"(d[2]), "+f"(d[3])
        : "r"(a[0]), "r"(a[1]), "r"(a[2]), "r"(a[3]), "r"(b[0]), "r"(b[1]));
}
__device__ __forceinline__ void cpasync16(uint32_t dst, const void* src, uint32_t sz) {
    asm volatile("cp.async.cg.shared.global [%0], [%1], 16, %2;"
                 :: "r"(dst), "l"(src), "r"(sz) : "memory");
}
#define CP_COMMIT() asm volatile("cp.async.commit_group;" ::: "memory")
#define CP_WAIT(n)  asm volatile("cp.async.wait_group %0;" :: "n"(n) : "memory")

// ---------------- software grid barrier ----------------
__device__ __forceinline__ void gbar() {
    __threadfence();
    __syncthreads();
    if (threadIdx.x == 0) {
        unsigned gen = *(volatile unsigned*)&g_bgen;
        if (atomicAdd(&g_bcnt, 1u) == NB - 1) {
            g_bcnt = 0;
            __threadfence();
            atomicExch(&g_bgen, gen + 1);
        } else {
            while (*(volatile unsigned*)&g_bgen == gen) {}
        }
    }
    __syncthreads();
    __threadfence();
}

// ---------------- fused CSR build ----------------
__global__ void __launch_bounds__(CSR_T)
csr_fused(const int* __restrict__ src, const int* __restrict__ dst) {
    int b = blockIdx.x, t = threadIdx.x;
    int gt = b * CSR_T + t;
    const int gstride = NB * CSR_T;
    __shared__ int sc[CSR_T];

    for (int i = gt; i < NN; i += gstride) g_cnt[i] = 0;
    gbar();
    for (int e = gt; e < NE; e += gstride) atomicAdd(&g_cnt[dst[e]], 1);
    gbar();
    int i0 = b * CHUNK;
    int e0 = i0 + t * 2;
    int c0 = 0, c1 = 0;
    if (t * 2 < CHUNK) {
        if (e0 < NN) c0 = g_cnt[e0];
        if (t * 2 + 1 < CHUNK && e0 + 1 < NN) c1 = g_cnt[e0 + 1];
    }
    sc[t] = c0 + c1;
    __syncthreads();
    for (int off = 1; off < CSR_T; off <<= 1) {
        int v = (t >= off) ? sc[t - off] : 0;
        __syncthreads();
        sc[t] += v;
        __syncthreads();
    }
    int excl = t ? sc[t - 1] : 0;
    if (t == CSR_T - 1) g_bsum[b] = sc[t];
    gbar();
    if (b == 0) {
        sc[t] = (t < NB) ? g_bsum[t] : 0;
        __syncthreads();
        for (int off = 1; off < CSR_T; off <<= 1) {
            int v = (t >= off) ? sc[t - off] : 0;
            __syncthreads();
            sc[t] += v;
            __syncthreads();
        }
        if (t < NB) g_boff[t] = t ? sc[t - 1] : 0;
    }
    gbar();
    {
        int base = g_boff[b] + excl;
        if (t * 2 < CHUNK && e0 < NN) {
            g_rowptr[e0] = base;
            g_wr[e0] = base;
            g_dinv[e0] = 1.0f / (float)(c0 > 1 ? c0 : 1);
            if (t * 2 + 1 < CHUNK && e0 + 1 < NN) {
                g_rowptr[e0 + 1] = base + c0;
                g_wr[e0 + 1] = base + c0;
                g_dinv[e0 + 1] = 1.0f / (float)(c1 > 1 ? c1 : 1);
            }
        }
        if (b == 0 && t == 0) g_rowptr[NN] = NE;
    }
    gbar();
    for (int e = gt; e < NE; e += gstride) {
        int p = atomicAdd(&g_wr[dst[e]], 1);
        g_csr[p] = src[e];
    }
}

// ---------------- fused prep: input fp32->fp16 + all 3 weight images ----------------
__global__ void prep_kernel(const float* __restrict__ x, __half* __restrict__ xh,
                            const float* __restrict__ wl0, const float* __restrict__ wr0,
                            const float* __restrict__ wl1, const float* __restrict__ wr1,
                            const float* __restrict__ wl2, const float* __restrict__ wr2,
                            __half* __restrict__ Wt)
{
    int b = blockIdx.x;
    if (b < CONV_BLKS) {
        size_t i = (size_t)b * 256 + threadIdx.x;
        if (i >= (size_t)NN * 32) return;
        float4 v = *(const float4*)(x + i * 4);
        __half2 h0 = __floats2half2_rn(v.x, v.y);
        __half2 h1 = __floats2half2_rn(v.z, v.w);
        uint2 u; u.x = *(uint32_t*)&h0; u.y = *(uint32_t*)&h1;
        *(uint2*)(xh + i * 4) = u;
    } else {
        int wb = b - CONV_BLKS;     // 0..319 (2 n-values per block)
        const float *Wl, *Wr;
        int HO, loff;
        if (wb < 128)      { Wl = wl0; Wr = wr0; HO = 128; loff = 0;     }
        else if (wb < 256) { Wl = wl1; Wr = wr1; HO = 128; loff = 32768; wb -= 128; }
        else               { Wl = wl2; Wr = wr2; HO = 64;  loff = 65536; wb -= 256; }
        int n = wb * 2 + (threadIdx.x >> 7);
        int k = threadIdx.x & 127;
        const float* W = (n < HO) ? Wl : Wr;
        int nn = (n < HO) ? n : n - HO;
        Wt[loff + n * 128 + k] = __float2half_rn(W[k * HO + nn]);
    }
}

// ---------------- persistent fp16 HMMA GEMM (unchanged from R12) ----------------
__global__ void __launch_bounds__(512, 2)
gemm_pers(const __half* __restrict__ xh,
          const __half* __restrict__ Wt, const float* __restrict__ bias,
          __half* __restrict__ yl, float* __restrict__ yr, int M, int HO)
{
    extern __shared__ char smem[];
    const uint32_t sb = su32(smem);

    int tid = threadIdx.x;
    int wid = tid >> 5, lane = tid & 31;
    int ny = blockIdx.y;
    int hol = HO - ny * 128; hol = hol < 0 ? 0 : (hol > 128 ? 128 : hol);

    int wm = (wid & 3) * 32;
    int wn = (wid >> 2) * 32;

    int row = tid >> 2;
    int ub4 = (tid & 3) * 4;
    uint32_t soff[4];
#pragma unroll
    for (int j = 0; j < 4; j++) soff[j] = (uint32_t)(((ub4 + j) ^ (row & 7)) << 4);

    {
        const __half* wRow = Wt + (size_t)(ny * 128 + row) * 128;
        uint32_t d0 = sb + row * 256;
#pragma unroll
        for (int j = 0; j < 4; j++)
            cpasync16(d0 + soff[j], wRow + (ub4 + j) * 8, 16u);
    }
    int nt = (M + 127) >> 7;
    int step = gridDim.x;

    {
        int m = blockIdx.x * 128 + row;
        uint32_t sz = (m < M) ? 16u : 0u;
        const __half* aS = xh + (size_t)m * 128;
        uint32_t dA = sb + 32768 + row * 256;
#pragma unroll
        for (int j = 0; j < 4; j++)
            cpasync16(dA + soff[j], aS + (ub4 + j) * 8, sz);
    }
    CP_COMMIT();

    int rA = wm + (lane & 15);
    uint32_t arow[2]; int xr[2];
#pragma unroll
    for (int mi = 0; mi < 2; mi++) {
        int r = rA + mi * 16;
        arow[mi] = (uint32_t)(r * 256);
        xr[mi] = r & 7;
    }
    int rbB0 = wn + (lane & 7) + ((lane >> 4) << 3);
    uint32_t brow[2]; int xb[2];
#pragma unroll
    for (int nj = 0; nj < 2; nj++) {
        int rb = rbB0 + nj * 16;
        brow[nj] = (uint32_t)(rb * 256);
        xb[nj] = rb & 7;
    }
    int laneA = lane >> 4;
    int laneB = (lane >> 3) & 1;
    int r_lane = lane >> 2;
    int c_lane = (lane & 3) * 2;
    bool isl = (wn < hol);
    int cb_yr = wn - hol;

    int p = 0;
    for (int t = blockIdx.x; t < nt; t += step, p ^= 1) {
        int tn = t + step;
        if (tn < nt) {
            int m = tn * 128 + row;
            uint32_t sz = (m < M) ? 16u : 0u;
            const __half* aS = xh + (size_t)m * 128;
            uint32_t dA = sb + 32768 + (p ^ 1) * 32768 + row * 256;
#pragma unroll
            for (int j = 0; j < 4; j++)
                cpasync16(dA + soff[j], aS + (ub4 + j) * 8, sz);
        }
        CP_COMMIT();
        CP_WAIT(1);
        __syncthreads();

        float acc[8][4];
#pragma unroll
        for (int i = 0; i < 8; i++)
#pragma unroll
            for (int j = 0; j < 4; j++) acc[i][j] = 0.f;

        uint32_t ab = sb + 32768 + p * 32768;
        uint32_t bB = sb;

#pragma unroll
        for (int k16 = 0; k16 < 8; k16++) {
            int ua = (k16 << 1) + laneA;
            int ub = (k16 << 1) + laneB;
            uint32_t af[2][4], bf[2][4];
#pragma unroll
            for (int mi = 0; mi < 2; mi++)
                ldsm4(af[mi], ab + arow[mi] + (uint32_t)((ua ^ xr[mi]) << 4));
#pragma unroll
            for (int nj = 0; nj < 2; nj++)
                ldsm4(bf[nj], bB + brow[nj] + (uint32_t)((ub ^ xb[nj]) << 4));
#pragma unroll
            for (int mi = 0; mi < 2; mi++)
#pragma unroll
                for (int nj2 = 0; nj2 < 4; nj2++)
                    mma16816h(acc[mi * 4 + nj2], af[mi], &bf[nj2 >> 1][(nj2 & 1) * 2]);
        }

        int m0 = t * 128;
        if (isl) {
#pragma unroll
            for (int mi = 0; mi < 2; mi++) {
                int mb = m0 + wm + mi * 16 + r_lane;
#pragma unroll
                for (int nj2 = 0; nj2 < 4; nj2++) {
                    float* d = acc[mi * 4 + nj2];
                    int col = wn + nj2 * 8 + c_lane;
                    __half2 h01 = __floats2half2_rn(d[0], d[1]);
                    __half2 h23 = __floats2half2_rn(d[2], d[3]);
                    if (mb < M)     *(__half2*)(yl + (size_t)mb * HO + col) = h01;
                    if (mb + 8 < M) *(__half2*)(yl + (size_t)(mb + 8) * HO + col) = h23;
                }
            }
        } else {
#pragma unroll
            for (int mi = 0; mi < 2; mi++) {
                int mb = m0 + wm + mi * 16 + r_lane;
#pragma unroll
                for (int nj2 = 0; nj2 < 4; nj2++) {
                    float* d = acc[mi * 4 + nj2];
                    int col = cb_yr + nj2 * 8 + c_lane;
                    float2 bv = *(const float2*)(bias + col);
                    float2 v01 = make_float2(d[0] + bv.x, d[1] + bv.y);
                    float2 v23 = make_float2(d[2] + bv.x, d[3] + bv.y);
                    if (mb < M)     *(float2*)(yr + (size_t)mb * HO + col) = v01;
                    if (mb + 8 < M) *(float2*)(yr + (size_t)(mb + 8) * HO + col) = v23;
                }
            }
        }
        __syncthreads();
    }
}

// ---------------- aggregation (H=128): vectorized index loads ----------------
__global__ void agg128_kernel(const __half* __restrict__ yl, const float* __restrict__ yrv,
                              __half* __restrict__ xh, int M)
{
    int gw = (blockIdx.x * blockDim.x + threadIdx.x) >> 5;
    int lane = threadIdx.x & 31;
    if (gw >= M) return;
    int beg = g_rowptr[gw], end = g_rowptr[gw + 1];
    float di = g_dinv[gw];

    float a0 = 0.f, a1 = 0.f, a2 = 0.f, a3 = 0.f;
    const __half* base = yl + lane * 4;
    int e = beg;
    // peel to int4 alignment
    for (; e < end && (e & 3); e++) {
        uint2 r0 = *(const uint2*)(base + (size_t)g_csr[e] * 128);
        float2 f0 = __half22float2(*(__half2*)&r0.x), f1 = __half22float2(*(__half2*)&r0.y);
        a0 += f0.x; a1 += f0.y; a2 += f1.x; a3 += f1.y;
    }
    for (; e + 8 <= end; e += 8) {
        int4 i0 = *(const int4*)(g_csr + e);
        int4 i1 = *(const int4*)(g_csr + e + 4);
        int s[8] = {i0.x, i0.y, i0.z, i0.w, i1.x, i1.y, i1.z, i1.w};
        uint2 r[8];
#pragma unroll
        for (int j = 0; j < 8; j++) r[j] = *(const uint2*)(base + (size_t)s[j] * 128);
#pragma unroll
        for (int j = 0; j < 8; j++) {
            float2 f0 = __half22float2(*(__half2*)&r[j].x), f1 = __half22float2(*(__half2*)&r[j].y);
            a0 += f0.x; a1 += f0.y; a2 += f1.x; a3 += f1.y;
        }
    }
    for (; e + 4 <= end; e += 4) {
        int4 i0 = *(const int4*)(g_csr + e);
        int s[4] = {i0.x, i0.y, i0.z, i0.w};
        uint2 r[4];
#pragma unroll
        for (int j = 0; j < 4; j++) r[j] = *(const uint2*)(base + (size_t)s[j] * 128);
#pragma unroll
        for (int j = 0; j < 4; j++) {
            float2 f0 = __half22float2(*(__half2*)&r[j].x), f1 = __half22float2(*(__half2*)&r[j].y);
            a0 += f0.x; a1 += f0.y; a2 += f1.x; a3 += f1.y;
        }
    }
    for (; e < end; e++) {
        uint2 r0 = *(const uint2*)(base + (size_t)g_csr[e] * 128);
        float2 f0 = __half22float2(*(__half2*)&r0.x), f1 = __half22float2(*(__half2*)&r0.y);
        a0 += f0.x; a1 += f0.y; a2 += f1.x; a3 += f1.y;
    }
    float4 r = *(const float4*)(yrv + (size_t)gw * 128 + lane * 4);
    float v0 = fmaxf(a0 * di + r.x, 0.f);
    float v1 = fmaxf(a1 * di + r.y, 0.f);
    float v2 = fmaxf(a2 * di + r.z, 0.f);
    float v3 = fmaxf(a3 * di + r.w, 0.f);

    __half2 h0 = __floats2half2_rn(v0, v1);
    __half2 h1 = __floats2half2_rn(v2, v3);
    uint2 u; u.x = *(uint32_t*)&h0; u.y = *(uint32_t*)&h1;
    *(uint2*)(xh + (size_t)gw * 128 + lane * 4) = u;
}

// ---------------- aggregation (H=64) fused with classifier head ----------------
__global__ void agg64_head_kernel(const __half* __restrict__ yl, const float* __restrict__ yrv,
                                  const float* __restrict__ wout, const float* __restrict__ bout,
                                  float* __restrict__ out, int M)
{
    __shared__ float ws[256];
    __shared__ float bs[4];
    int t = threadIdx.x;
    ws[t] = wout[t];
    if (t < 4) bs[t] = bout[t];
    __syncthreads();
    int gw = blockIdx.x * 8 + (t >> 5);
    int lane = t & 31;
    if (gw >= M) return;
    int beg = g_rowptr[gw], end = g_rowptr[gw + 1];
    float di = g_dinv[gw];

    float a0 = 0.f, a1 = 0.f;
    const __half* base = yl + lane * 2;
    int e = beg;
    for (; e < end && (e & 3); e++) {
        float2 f0 = __half22float2(*(const __half2*)(base + (size_t)g_csr[e] * 64));
        a0 += f0.x; a1 += f0.y;
    }
    for (; e + 4 <= end; e += 4) {
        int4 i0 = *(const int4*)(g_csr + e);
        int s[4] = {i0.x, i0.y, i0.z, i0.w};
        float2 f[4];
#pragma unroll
        for (int j = 0; j < 4; j++) f[j] = __half22float2(*(const __half2*)(base + (size_t)s[j] * 64));
        a0 += (f[0].x + f[1].x) + (f[2].x + f[3].x);
        a1 += (f[0].y + f[1].y) + (f[2].y + f[3].y);
    }
    for (; e < end; e++) {
        float2 f0 = __half22float2(*(const __half2*)(base + (size_t)g_csr[e] * 64));
        a0 += f0.x; a1 += f0.y;
    }
    float2 r = *(const float2*)(yrv + (size_t)gw * 64 + lane * 2);
    float v0 = fmaxf(a0 * di + r.x, 0.f);
    float v1 = fmaxf(a1 * di + r.y, 0.f);

    float acc[4];
#pragma unroll
    for (int c = 0; c < 4; c++)
        acc[c] = v0 * ws[(lane * 2) * 4 + c] + v1 * ws[(lane * 2 + 1) * 4 + c];
#pragma unroll
    for (int off = 16; off > 0; off >>= 1) {
#pragma unroll
        for (int c = 0; c < 4; c++)
            acc[c] += __shfl_xor_sync(0xFFFFFFFF, acc[c], off);
    }
    if (lane == 0) {
        float4 o = make_float4(acc[0] + bs[0], acc[1] + bs[1], acc[2] + bs[2], acc[3] + bs[3]);
        *(float4*)(out + (size_t)gw * 4) = o;
    }
}

// ---------------- launch ----------------
extern "C" void kernel_launch(void* const* d_in, const int* in_sizes, int n_in,
                              void* d_out, int out_size)
{
    (void)in_sizes; (void)n_in; (void)out_size;
    const float* x     = (const float*)d_in[0];
    const int*   ei    = (const int*)d_in[1];
    const float* w_l0  = (const float*)d_in[3];
    const float* w_r0  = (const float*)d_in[4];
    const float* b0    = (const float*)d_in[5];
    const float* w_l1  = (const float*)d_in[6];
    const float* w_r1  = (const float*)d_in[7];
    const float* b1    = (const float*)d_in[8];
    const float* w_l2  = (const float*)d_in[9];
    const float* w_r2  = (const float*)d_in[10];
    const float* b2    = (const float*)d_in[11];
    const float* w_out = (const float*)d_in[12];
    const float* b_out = (const float*)d_in[13];
    float* out = (float*)d_out;

    const int* srcp = ei;
    const int* dstp = ei + NE;

    __half *xh, *ylh, *wt;
    float* yrf;
    cudaGetSymbolAddress((void**)&xh,  g_xh);
    cudaGetSymbolAddress((void**)&ylh, g_ylh);
    cudaGetSymbolAddress((void**)&yrf, g_yrf);
    cudaGetSymbolAddress((void**)&wt,  g_wt);

    static cudaStream_t s2 = nullptr;
    static cudaEvent_t evFork = nullptr, evJoin = nullptr;
    if (!s2) {
        cudaStreamCreateWithFlags(&s2, cudaStreamNonBlocking);
        cudaEventCreateWithFlags(&evFork, cudaEventDisableTiming);
        cudaEventCreateWithFlags(&evJoin, cudaEventDisableTiming);
        cudaFuncSetAttribute(gemm_pers, cudaFuncAttributeMaxDynamicSharedMemorySize, 98304);
    }

    int ablk = (NN + 7) / 8;

    cudaEventRecord(evFork, 0);
    cudaStreamWaitEvent(s2, evFork, 0);

    // #1 (s2): fused CSR build
    csr_fused<<<NB, CSR_T, 0, s2>>>(srcp, dstp);
    cudaEventRecord(evJoin, s2);
    // #2 (main): fused prep (input fp16 + 3 weight images)
    prep_kernel<<<CONV_BLKS + 320, 256>>>(x, xh, w_l0, w_r0, w_l1, w_r1, w_l2, w_r2, wt);
    // #3 (main): layer-0 GEMM
    gemm_pers<<<dim3(148, 2), 512, 98304>>>(xh, wt, b0, ylh, yrf, NN, 128);
    // join: aggregation needs CSR
    cudaStreamWaitEvent(0, evJoin, 0);
    // #4 (main): layer-0 aggregation  <-- ncu capture target
    agg128_kernel<<<ablk, 256>>>(ylh, yrf, xh, NN);
    // #5..#8
    gemm_pers<<<dim3(148, 2), 512, 98304>>>(xh, wt + 32768, b1, ylh, yrf, NN, 128);
    agg128_kernel<<<ablk, 256>>>(ylh, yrf, xh, NN);
    gemm_pers<<<dim3(296, 1), 512, 98304>>>(xh, wt + 65536, b2, ylh, yrf, NN, 64);
    agg64_head_kernel<<<ablk, 256>>>(ylh, yrf, w_out, b_out, out, NN);
}

// round 14
// speedup vs baseline: 1.0766x; 1.0766x over previous
#include <cuda_runtime.h>
#include <cuda_fp16.h>
#include <cstdint>
#include <cstddef>

#define NN 50000
#define NE 800000
#define CONV_BLKS ((NN * 32 + 255) / 256)
#define NB 148
#define CSR_T 256
#define CHUNK 338   // 148*338 = 50024 >= 50000

// ---------------- scratch (static device globals) ----------------
__device__ int   g_cnt[NN];
__device__ int   g_rowptr[NN + 1];
__device__ int   g_wr[NN];
__device__ int   g_csr[NE];
__device__ float g_dinv[NN];
__device__ __half g_xh[(size_t)NN * 128];
__device__ __half g_ylh[(size_t)NN * 128];
__device__ float  g_yrf[(size_t)NN * 128];
__device__ __half g_wt[2 * 256 * 128 + 128 * 128];   // L0,L1: 256x128 ; L2: 128x128
__device__ unsigned g_bgen = 0;
__device__ unsigned g_bcnt = 0;
__device__ int g_bsum[NB];
__device__ int g_boff[NB];

// ---------------- PTX helpers (base ISA only) ----------------
__device__ __forceinline__ uint32_t su32(const void* p) {
    uint32_t a;
    asm("{ .reg .u64 t; cvta.to.shared.u64 t, %1; cvt.u32.u64 %0, t; }" : "=r"(a) : "l"(p));
    return a;
}
__device__ __forceinline__ void ldsm4(uint32_t* r, uint32_t addr) {
    asm volatile("ldmatrix.sync.aligned.m8n8.x4.shared.b16 {%0,%1,%2,%3}, [%4];"
                 : "=r"(r[0]), "=r"(r[1]), "=r"(r[2]), "=r"(r[3]) : "r"(addr));
}
__device__ __forceinline__ void mma16816h(float* d, const uint32_t* a, const uint32_t* b) {
    asm volatile(
        "mma.sync.aligned.m16n8k16.row.col.f32.f16.f16.f32 "
        "{%0,%1,%2,%3}, {%4,%5,%6,%7}, {%8,%9}, {%0,%1,%2,%3};"
        : "+f"(d[0]), "+f"(d[1]), "+f"(d[2]), "+f"(d[3])
        : "r"(a[0]), "r"(a[1]), "r"(a[2]), "r"(a[3]), "r"(b[0]), "r"(b[1]));
}
__device__ __forceinline__ void cpasync16(uint32_t dst, const void* src, uint32_t sz) {
    asm volatile("cp.async.cg.shared.global [%0], [%1], 16, %2;"
                 :: "r"(dst), "l"(src), "r"(sz) : "memory");
}
#define CP_COMMIT() asm volatile("cp.async.commit_group;" ::: "memory")
#define CP_WAIT(n)  asm volatile("cp.async.wait_group %0;" :: "n"(n) : "memory")

// ---------------- software grid barrier ----------------
__device__ __forceinline__ void gbar() {
    __threadfence();
    __syncthreads();
    if (threadIdx.x == 0) {
        unsigned gen = *(volatile unsigned*)&g_bgen;
        if (atomicAdd(&g_bcnt, 1u) == NB - 1) {
            g_bcnt = 0;
            __threadfence();
            atomicExch(&g_bgen, gen + 1);
        } else {
            while (*(volatile unsigned*)&g_bgen == gen) {}
        }
    }
    __syncthreads();
    __threadfence();
}

// ---------------- fused CSR build ----------------
__global__ void __launch_bounds__(CSR_T)
csr_fused(const int* __restrict__ src, const int* __restrict__ dst) {
    int b = blockIdx.x, t = threadIdx.x;
    int gt = b * CSR_T + t;
    const int gstride = NB * CSR_T;
    __shared__ int sc[CSR_T];

    for (int i = gt; i < NN; i += gstride) g_cnt[i] = 0;
    gbar();
    for (int e = gt; e < NE; e += gstride) atomicAdd(&g_cnt[dst[e]], 1);
    gbar();
    int i0 = b * CHUNK;
    int e0 = i0 + t * 2;
    int c0 = 0, c1 = 0;
    if (t * 2 < CHUNK) {
        if (e0 < NN) c0 = g_cnt[e0];
        if (t * 2 + 1 < CHUNK && e0 + 1 < NN) c1 = g_cnt[e0 + 1];
    }
    sc[t] = c0 + c1;
    __syncthreads();
    for (int off = 1; off < CSR_T; off <<= 1) {
        int v = (t >= off) ? sc[t - off] : 0;
        __syncthreads();
        sc[t] += v;
        __syncthreads();
    }
    int excl = t ? sc[t - 1] : 0;
    if (t == CSR_T - 1) g_bsum[b] = sc[t];
    gbar();
    if (b == 0) {
        sc[t] = (t < NB) ? g_bsum[t] : 0;
        __syncthreads();
        for (int off = 1; off < CSR_T; off <<= 1) {
            int v = (t >= off) ? sc[t - off] : 0;
            __syncthreads();
            sc[t] += v;
            __syncthreads();
        }
        if (t < NB) g_boff[t] = t ? sc[t - 1] : 0;
    }
    gbar();
    {
        int base = g_boff[b] + excl;
        if (t * 2 < CHUNK && e0 < NN) {
            g_rowptr[e0] = base;
            g_wr[e0] = base;
            g_dinv[e0] = 1.0f / (float)(c0 > 1 ? c0 : 1);
            if (t * 2 + 1 < CHUNK && e0 + 1 < NN) {
                g_rowptr[e0 + 1] = base + c0;
                g_wr[e0 + 1] = base + c0;
                g_dinv[e0 + 1] = 1.0f / (float)(c1 > 1 ? c1 : 1);
            }
        }
        if (b == 0 && t == 0) g_rowptr[NN] = NE;
    }
    gbar();
    for (int e = gt; e < NE; e += gstride) {
        int p = atomicAdd(&g_wr[dst[e]], 1);
        g_csr[p] = src[e];
    }
}

// ---------------- fused prep: input fp32->fp16 + all 3 weight images ----------------
__global__ void prep_kernel(const float* __restrict__ x, __half* __restrict__ xh,
                            const float* __restrict__ wl0, const float* __restrict__ wr0,
                            const float* __restrict__ wl1, const float* __restrict__ wr1,
                            const float* __restrict__ wl2, const float* __restrict__ wr2,
                            __half* __restrict__ Wt)
{
    int b = blockIdx.x;
    if (b < CONV_BLKS) {
        size_t i = (size_t)b * 256 + threadIdx.x;
        if (i >= (size_t)NN * 32) return;
        float4 v = *(const float4*)(x + i * 4);
        __half2 h0 = __floats2half2_rn(v.x, v.y);
        __half2 h1 = __floats2half2_rn(v.z, v.w);
        uint2 u; u.x = *(uint32_t*)&h0; u.y = *(uint32_t*)&h1;
        *(uint2*)(xh + i * 4) = u;
    } else {
        int wb = b - CONV_BLKS;     // 0..319 (2 n-values per block)
        const float *Wl, *Wr;
        int HO, loff;
        if (wb < 128)      { Wl = wl0; Wr = wr0; HO = 128; loff = 0;     }
        else if (wb < 256) { Wl = wl1; Wr = wr1; HO = 128; loff = 32768; wb -= 128; }
        else               { Wl = wl2; Wr = wr2; HO = 64;  loff = 65536; wb -= 256; }
        int n = wb * 2 + (threadIdx.x >> 7);
        int k = threadIdx.x & 127;
        const float* W = (n < HO) ? Wl : Wr;
        int nn = (n < HO) ? n : n - HO;
        Wt[loff + n * 128 + k] = __float2half_rn(W[k * HO + nn]);
    }
}

// ---------------- persistent fp16 HMMA GEMM (unchanged from R12) ----------------
__global__ void __launch_bounds__(512, 2)
gemm_pers(const __half* __restrict__ xh,
          const __half* __restrict__ Wt, const float* __restrict__ bias,
          __half* __restrict__ yl, float* __restrict__ yr, int M, int HO)
{
    extern __shared__ char smem[];
    const uint32_t sb = su32(smem);

    int tid = threadIdx.x;
    int wid = tid >> 5, lane = tid & 31;
    int ny = blockIdx.y;
    int hol = HO - ny * 128; hol = hol < 0 ? 0 : (hol > 128 ? 128 : hol);

    int wm = (wid & 3) * 32;
    int wn = (wid >> 2) * 32;

    int row = tid >> 2;
    int ub4 = (tid & 3) * 4;
    uint32_t soff[4];
#pragma unroll
    for (int j = 0; j < 4; j++) soff[j] = (uint32_t)(((ub4 + j) ^ (row & 7)) << 4);

    {
        const __half* wRow = Wt + (size_t)(ny * 128 + row) * 128;
        uint32_t d0 = sb + row * 256;
#pragma unroll
        for (int j = 0; j < 4; j++)
            cpasync16(d0 + soff[j], wRow + (ub4 + j) * 8, 16u);
    }
    int nt = (M + 127) >> 7;
    int step = gridDim.x;

    {
        int m = blockIdx.x * 128 + row;
        uint32_t sz = (m < M) ? 16u : 0u;
        const __half* aS = xh + (size_t)m * 128;
        uint32_t dA = sb + 32768 + row * 256;
#pragma unroll
        for (int j = 0; j < 4; j++)
            cpasync16(dA + soff[j], aS + (ub4 + j) * 8, sz);
    }
    CP_COMMIT();

    int rA = wm + (lane & 15);
    uint32_t arow[2]; int xr[2];
#pragma unroll
    for (int mi = 0; mi < 2; mi++) {
        int r = rA + mi * 16;
        arow[mi] = (uint32_t)(r * 256);
        xr[mi] = r & 7;
    }
    int rbB0 = wn + (lane & 7) + ((lane >> 4) << 3);
    uint32_t brow[2]; int xb[2];
#pragma unroll
    for (int nj = 0; nj < 2; nj++) {
        int rb = rbB0 + nj * 16;
        brow[nj] = (uint32_t)(rb * 256);
        xb[nj] = rb & 7;
    }
    int laneA = lane >> 4;
    int laneB = (lane >> 3) & 1;
    int r_lane = lane >> 2;
    int c_lane = (lane & 3) * 2;
    bool isl = (wn < hol);
    int cb_yr = wn - hol;

    int p = 0;
    for (int t = blockIdx.x; t < nt; t += step, p ^= 1) {
        int tn = t + step;
        if (tn < nt) {
            int m = tn * 128 + row;
            uint32_t sz = (m < M) ? 16u : 0u;
            const __half* aS = xh + (size_t)m * 128;
            uint32_t dA = sb + 32768 + (p ^ 1) * 32768 + row * 256;
#pragma unroll
            for (int j = 0; j < 4; j++)
                cpasync16(dA + soff[j], aS + (ub4 + j) * 8, sz);
        }
        CP_COMMIT();
        CP_WAIT(1);
        __syncthreads();

        float acc[8][4];
#pragma unroll
        for (int i = 0; i < 8; i++)
#pragma unroll
            for (int j = 0; j < 4; j++) acc[i][j] = 0.f;

        uint32_t ab = sb + 32768 + p * 32768;
        uint32_t bB = sb;

#pragma unroll
        for (int k16 = 0; k16 < 8; k16++) {
            int ua = (k16 << 1) + laneA;
            int ub = (k16 << 1) + laneB;
            uint32_t af[2][4], bf[2][4];
#pragma unroll
            for (int mi = 0; mi < 2; mi++)
                ldsm4(af[mi], ab + arow[mi] + (uint32_t)((ua ^ xr[mi]) << 4));
#pragma unroll
            for (int nj = 0; nj < 2; nj++)
                ldsm4(bf[nj], bB + brow[nj] + (uint32_t)((ub ^ xb[nj]) << 4));
#pragma unroll
            for (int mi = 0; mi < 2; mi++)
#pragma unroll
                for (int nj2 = 0; nj2 < 4; nj2++)
                    mma16816h(acc[mi * 4 + nj2], af[mi], &bf[nj2 >> 1][(nj2 & 1) * 2]);
        }

        int m0 = t * 128;
        if (isl) {
#pragma unroll
            for (int mi = 0; mi < 2; mi++) {
                int mb = m0 + wm + mi * 16 + r_lane;
#pragma unroll
                for (int nj2 = 0; nj2 < 4; nj2++) {
                    float* d = acc[mi * 4 + nj2];
                    int col = wn + nj2 * 8 + c_lane;
                    __half2 h01 = __floats2half2_rn(d[0], d[1]);
                    __half2 h23 = __floats2half2_rn(d[2], d[3]);
                    if (mb < M)     *(__half2*)(yl + (size_t)mb * HO + col) = h01;
                    if (mb + 8 < M) *(__half2*)(yl + (size_t)(mb + 8) * HO + col) = h23;
                }
            }
        } else {
#pragma unroll
            for (int mi = 0; mi < 2; mi++) {
                int mb = m0 + wm + mi * 16 + r_lane;
#pragma unroll
                for (int nj2 = 0; nj2 < 4; nj2++) {
                    float* d = acc[mi * 4 + nj2];
                    int col = cb_yr + nj2 * 8 + c_lane;
                    float2 bv = *(const float2*)(bias + col);
                    float2 v01 = make_float2(d[0] + bv.x, d[1] + bv.y);
                    float2 v23 = make_float2(d[2] + bv.x, d[3] + bv.y);
                    if (mb < M)     *(float2*)(yr + (size_t)mb * HO + col) = v01;
                    if (mb + 8 < M) *(float2*)(yr + (size_t)(mb + 8) * HO + col) = v23;
                }
            }
        }
        __syncthreads();
    }
}

// ---------------- aggregation (H=128): relu(mean + yr) -> fp16, 8-way unrolled (R12 form) ----------------
__global__ void agg128_kernel(const __half* __restrict__ yl, const float* __restrict__ yrv,
                              __half* __restrict__ xh, int M)
{
    int gw = (blockIdx.x * blockDim.x + threadIdx.x) >> 5;
    int lane = threadIdx.x & 31;
    if (gw >= M) return;
    int beg = g_rowptr[gw], end = g_rowptr[gw + 1];
    float di = g_dinv[gw];

    float a0 = 0.f, a1 = 0.f, a2 = 0.f, a3 = 0.f;
    const __half* base = yl + lane * 4;
    int e = beg;
    for (; e + 8 <= end; e += 8) {
        int s[8];
#pragma unroll
        for (int j = 0; j < 8; j++) s[j] = g_csr[e + j];
        uint2 r[8];
#pragma unroll
        for (int j = 0; j < 8; j++) r[j] = *(const uint2*)(base + (size_t)s[j] * 128);
#pragma unroll
        for (int j = 0; j < 8; j++) {
            float2 f0 = __half22float2(*(__half2*)&r[j].x), f1 = __half22float2(*(__half2*)&r[j].y);
            a0 += f0.x; a1 += f0.y; a2 += f1.x; a3 += f1.y;
        }
    }
    for (; e + 4 <= end; e += 4) {
        int s[4];
#pragma unroll
        for (int j = 0; j < 4; j++) s[j] = g_csr[e + j];
        uint2 r[4];
#pragma unroll
        for (int j = 0; j < 4; j++) r[j] = *(const uint2*)(base + (size_t)s[j] * 128);
#pragma unroll
        for (int j = 0; j < 4; j++) {
            float2 f0 = __half22float2(*(__half2*)&r[j].x), f1 = __half22float2(*(__half2*)&r[j].y);
            a0 += f0.x; a1 += f0.y; a2 += f1.x; a3 += f1.y;
        }
    }
    for (; e < end; e++) {
        uint2 r0 = *(const uint2*)(base + (size_t)g_csr[e] * 128);
        float2 f0 = __half22float2(*(__half2*)&r0.x), f1 = __half22float2(*(__half2*)&r0.y);
        a0 += f0.x; a1 += f0.y; a2 += f1.x; a3 += f1.y;
    }
    float4 r = *(const float4*)(yrv + (size_t)gw * 128 + lane * 4);
    float v0 = fmaxf(a0 * di + r.x, 0.f);
    float v1 = fmaxf(a1 * di + r.y, 0.f);
    float v2 = fmaxf(a2 * di + r.z, 0.f);
    float v3 = fmaxf(a3 * di + r.w, 0.f);

    __half2 h0 = __floats2half2_rn(v0, v1);
    __half2 h1 = __floats2half2_rn(v2, v3);
    uint2 u; u.x = *(uint32_t*)&h0; u.y = *(uint32_t*)&h1;
    *(uint2*)(xh + (size_t)gw * 128 + lane * 4) = u;
}

// ---------------- aggregation (H=64) fused with classifier head (R12 form) ----------------
__global__ void agg64_head_kernel(const __half* __restrict__ yl, const float* __restrict__ yrv,
                                  const float* __restrict__ wout, const float* __restrict__ bout,
                                  float* __restrict__ out, int M)
{
    __shared__ float ws[256];
    __shared__ float bs[4];
    int t = threadIdx.x;
    ws[t] = wout[t];
    if (t < 4) bs[t] = bout[t];
    __syncthreads();
    int gw = blockIdx.x * 8 + (t >> 5);
    int lane = t & 31;
    if (gw >= M) return;
    int beg = g_rowptr[gw], end = g_rowptr[gw + 1];
    float di = g_dinv[gw];

    float a0 = 0.f, a1 = 0.f;
    const __half* base = yl + lane * 2;
    int e = beg;
    for (; e + 4 <= end; e += 4) {
        int s0 = g_csr[e], s1 = g_csr[e + 1], s2 = g_csr[e + 2], s3 = g_csr[e + 3];
        float2 f0 = __half22float2(*(const __half2*)(base + (size_t)s0 * 64));
        float2 f1 = __half22float2(*(const __half2*)(base + (size_t)s1 * 64));
        float2 f2 = __half22float2(*(const __half2*)(base + (size_t)s2 * 64));
        float2 f3 = __half22float2(*(const __half2*)(base + (size_t)s3 * 64));
        a0 += (f0.x + f1.x) + (f2.x + f3.x);
        a1 += (f0.y + f1.y) + (f2.y + f3.y);
    }
    for (; e < end; e++) {
        float2 f0 = __half22float2(*(const __half2*)(base + (size_t)g_csr[e] * 64));
        a0 += f0.x; a1 += f0.y;
    }
    float2 r = *(const float2*)(yrv + (size_t)gw * 64 + lane * 2);
    float v0 = fmaxf(a0 * di + r.x, 0.f);
    float v1 = fmaxf(a1 * di + r.y, 0.f);

    float acc[4];
#pragma unroll
    for (int c = 0; c < 4; c++)
        acc[c] = v0 * ws[(lane * 2) * 4 + c] + v1 * ws[(lane * 2 + 1) * 4 + c];
#pragma unroll
    for (int off = 16; off > 0; off >>= 1) {
#pragma unroll
        for (int c = 0; c < 4; c++)
            acc[c] += __shfl_xor_sync(0xFFFFFFFF, acc[c], off);
    }
    if (lane == 0) {
        float4 o = make_float4(acc[0] + bs[0], acc[1] + bs[1], acc[2] + bs[2], acc[3] + bs[3]);
        *(float4*)(out + (size_t)gw * 4) = o;
    }
}

// ---------------- launch ----------------
extern "C" void kernel_launch(void* const* d_in, const int* in_sizes, int n_in,
                              void* d_out, int out_size)
{
    (void)in_sizes; (void)n_in; (void)out_size;
    const float* x     = (const float*)d_in[0];
    const int*   ei    = (const int*)d_in[1];
    const float* w_l0  = (const float*)d_in[3];
    const float* w_r0  = (const float*)d_in[4];
    const float* b0    = (const float*)d_in[5];
    const float* w_l1  = (const float*)d_in[6];
    const float* w_r1  = (const float*)d_in[7];
    const float* b1    = (const float*)d_in[8];
    const float* w_l2  = (const float*)d_in[9];
    const float* w_r2  = (const float*)d_in[10];
    const float* b2    = (const float*)d_in[11];
    const float* w_out = (const float*)d_in[12];
    const float* b_out = (const float*)d_in[13];
    float* out = (float*)d_out;

    const int* srcp = ei;
    const int* dstp = ei + NE;

    __half *xh, *ylh, *wt;
    float* yrf;
    cudaGetSymbolAddress((void**)&xh,  g_xh);
    cudaGetSymbolAddress((void**)&ylh, g_ylh);
    cudaGetSymbolAddress((void**)&yrf, g_yrf);
    cudaGetSymbolAddress((void**)&wt,  g_wt);

    static cudaStream_t s2 = nullptr;
    static cudaEvent_t evFork = nullptr, evJoin = nullptr;
    if (!s2) {
        cudaStreamCreateWithFlags(&s2, cudaStreamNonBlocking);
        cudaEventCreateWithFlags(&evFork, cudaEventDisableTiming);
        cudaEventCreateWithFlags(&evJoin, cudaEventDisableTiming);
        cudaFuncSetAttribute(gemm_pers, cudaFuncAttributeMaxDynamicSharedMemorySize, 98304);
    }

    int ablk = (NN + 7) / 8;

    cudaEventRecord(evFork, 0);
    cudaStreamWaitEvent(s2, evFork, 0);

    // #1 (s2): fused CSR build
    csr_fused<<<NB, CSR_T, 0, s2>>>(srcp, dstp);
    cudaEventRecord(evJoin, s2);
    // #2 (main): fused prep (input fp16 + 3 weight images)
    prep_kernel<<<CONV_BLKS + 320, 256>>>(x, xh, w_l0, w_r0, w_l1, w_r1, w_l2, w_r2, wt);
    // #3 (main): layer-0 GEMM
    gemm_pers<<<dim3(148, 2), 512, 98304>>>(xh, wt, b0, ylh, yrf, NN, 128);
    // join: aggregation needs CSR
    cudaStreamWaitEvent(0, evJoin, 0);
    // #4 (main): layer-0 aggregation  <-- ncu capture target
    agg128_kernel<<<ablk, 256>>>(ylh, yrf, xh, NN);
    // #5..#8
    gemm_pers<<<dim3(148, 2), 512, 98304>>>(xh, wt + 32768, b1, ylh, yrf, NN, 128);
    agg128_kernel<<<ablk, 256>>>(ylh, yrf, xh, NN);
    gemm_pers<<<dim3(296, 1), 512, 98304>>>(xh, wt + 65536, b2, ylh, yrf, NN, 64);
    agg64_head_kernel<<<ablk, 256>>>(ylh, yrf, w_out, b_out, out, NN);
}